// round 14
// baseline (speedup 1.0000x reference)
#include <cuda_runtime.h>
#include <cuda_bf16.h>
#include <stdint.h>

// ---------------- constants ----------------
#define NR   8192
#define DD   1024
#define TM   128           // tile rows (Q block)
#define TN   128           // tile cols (K block)
#define NBI  (NR / TM)     // 64 row blocks
#define NBJ  (NR / TN)     // 64 col blocks
#define KB   128           // bytes per k-chunk per row = 128 fp8 = SW128 atom row
#define NITER (DD / KB)    // 8 chunks
#define NSTAGE 3
#define THREADS 256
#define A_BYTES (TM * 128)             // 16384
#define B_BYTES (TN * 128)             // 16384
#define STAGE_BYTES (A_BYTES + B_BYTES)
#define SMEM_TOTAL (NSTAGE * STAGE_BYTES)   // 98304 -> 2 CTAs/SM

#define INV_T 14.285714285714286f
#define C1    20.609929155556602f      /* (1/0.07) * log2(e) */
#define QSCALE (1.0f / 64.0f)          /* vectors scaled by 8 -> dot scaled by 64 */
#define RBLK 32                        /* reduce kernel blocks */

// ---------------- device scratch (static only) ----------------
__device__ __align__(256) char g_q8[NR * DD];
__device__ __align__(256) char g_k8[NR * DD];
__device__ float g_row_part[NBJ * NR];   // [col-block j][global row]
__device__ float g_col_part[NBI * NR];   // [row-block i][global col]
__device__ float g_diag[NR];
__device__ float g_block_part[RBLK];
__device__ unsigned int g_ticket = 0;

// ---------------- helpers ----------------
__device__ __forceinline__ uint32_t smem_u32(const void* p) {
    uint32_t a;
    asm("{ .reg .u64 t; cvta.to.shared.u64 t, %1; cvt.u32.u64 %0, t; }" : "=r"(a) : "l"(p));
    return a;
}

__device__ __forceinline__ void cp16(uint32_t dst, const void* src) {
    asm volatile("cp.async.cg.shared.global [%0], [%1], 16;" :: "r"(dst), "l"(src) : "memory");
}

__device__ __forceinline__ void ldsm4(uint32_t (&r)[4], uint32_t addr) {
    asm volatile("ldmatrix.sync.aligned.m8n8.x4.shared.b16 {%0,%1,%2,%3}, [%4];"
                 : "=r"(r[0]), "=r"(r[1]), "=r"(r[2]), "=r"(r[3]) : "r"(addr));
}

// fp8 e4m3 MMA m16n8k32, f32 accum
__device__ __forceinline__ void mma_fp8(float (&c)[4], const uint32_t (&a)[4],
                                        uint32_t b0, uint32_t b1) {
    asm volatile(
        "mma.sync.aligned.m16n8k32.row.col.f32.e4m3.e4m3.f32 "
        "{%0,%1,%2,%3}, {%4,%5,%6,%7}, {%8,%9}, {%0,%1,%2,%3};"
        : "+f"(c[0]), "+f"(c[1]), "+f"(c[2]), "+f"(c[3])
        : "r"(a[0]), "r"(a[1]), "r"(a[2]), "r"(a[3]), "r"(b0), "r"(b1));
}

// fast exp2 on the FMA pipe (no MUFU); y in [-42, ~0.5] here
__device__ __forceinline__ float exp2_fast(float y) {
    float t = y + 12582912.0f;                       // 1.5 * 2^23
    int   n = __float_as_int(t) - __float_as_int(12582912.0f);
    float f = y - (t - 12582912.0f);                 // [-0.5, 0.5]
    float p = 1.3333558146e-3f;
    p = fmaf(p, f, 9.6181291076e-3f);
    p = fmaf(p, f, 5.5504108664e-2f);
    p = fmaf(p, f, 2.4022650696e-1f);
    p = fmaf(p, f, 6.9314718056e-1f);
    p = fmaf(p, f, 1.0f);
    return __int_as_float(__float_as_int(p) + (n << 23));
}

// ---------------- kernel 1: L2-normalize rows -> e4m3 (warp per row) ----------------
__global__ void __launch_bounds__(256) norm_kernel(const float* __restrict__ q,
                                                   const float* __restrict__ k) {
    const int wid = threadIdx.x >> 5, lane = threadIdx.x & 31;
    const int gw = blockIdx.x * 8 + wid;          // 0 .. 2*NR-1
    const bool is_k = gw >= NR;
    const int row = is_k ? gw - NR : gw;
    const float4* src = reinterpret_cast<const float4*>((is_k ? k : q) + (size_t)row * DD);
    uint32_t* dst = reinterpret_cast<uint32_t*>((is_k ? g_k8 : g_q8) + (size_t)row * DD);

    float4 v[8];
    float s = 0.f;
    #pragma unroll
    for (int i = 0; i < 8; i++) {
        v[i] = __ldcs(&src[lane + 32 * i]);   // evict-first: source read once, keep L2 for fp8
        s += v[i].x * v[i].x + v[i].y * v[i].y + v[i].z * v[i].z + v[i].w * v[i].w;
    }
    #pragma unroll
    for (int o = 16; o; o >>= 1) s += __shfl_xor_sync(0xffffffffu, s, o);
    const float inv = 8.0f / fmaxf(sqrtf(s), 1e-12f);

    #pragma unroll
    for (int i = 0; i < 8; i++) {
        uint16_t lo, hi;
        asm("cvt.rn.satfinite.e4m3x2.f32 %0, %1, %2;" : "=h"(lo) : "f"(v[i].y * inv), "f"(v[i].x * inv));
        asm("cvt.rn.satfinite.e4m3x2.f32 %0, %1, %2;" : "=h"(hi) : "f"(v[i].w * inv), "f"(v[i].z * inv));
        dst[lane + 32 * i] = (uint32_t)lo | ((uint32_t)hi << 16);
    }
}

// ---------------- kernel 2: fused FP8 MMA tile (128x128, 2 CTAs/SM) ----------------
extern __shared__ char sm_raw[];

__device__ __forceinline__ void load_chunk(uint32_t sbase, int chunk, int stage,
                                           int bi, int bj, int tid) {
    uint32_t bufA = sbase + stage * STAGE_BYTES;
    uint32_t bufB = bufA + A_BYTES;
    const char* gA = g_q8 + (size_t)(bi * TM) * DD + chunk * KB;
    const char* gB = g_k8 + (size_t)(bj * TN) * DD + chunk * KB;
    #pragma unroll
    for (int u = 0; u < 4; u++) {            // A: 1024 x 16B
        int idx = tid + u * THREADS;
        int row = idx >> 3, seg = idx & 7;
        cp16(bufA + row * 128 + ((seg ^ (row & 7)) << 4),
             gA + (size_t)row * DD + seg * 16);
    }
    #pragma unroll
    for (int u = 0; u < 4; u++) {            // B: 1024 x 16B
        int idx = tid + u * THREADS;
        int row = idx >> 3, seg = idx & 7;
        cp16(bufB + row * 128 + ((seg ^ (row & 7)) << 4),
             gB + (size_t)row * DD + seg * 16);
    }
}

__global__ void __launch_bounds__(THREADS, 2) gemm_tile_kernel() {
    const int tid = threadIdx.x;
    const int bi = blockIdx.y;     // Q block: rows bi*128..+127
    const int bj = blockIdx.x;     // K block: cols bj*128..+127
    const uint32_t sbase = smem_u32(sm_raw);

    const int wid  = tid >> 5, lane = tid & 31;
    const int mw   = wid >> 2;     // 0..1 : 64-row strip
    const int nw   = wid & 3;      // 0..3 : 32-col strip
    const int lrow = lane & 15;    // row within 16-row frag
    const int lhalf = lane >> 4;   // 16B half within k32

    float acc[4][4][4];
    #pragma unroll
    for (int mf = 0; mf < 4; mf++)
        #pragma unroll
        for (int nf = 0; nf < 4; nf++)
            #pragma unroll
            for (int e = 0; e < 4; e++) acc[mf][nf][e] = 0.f;

    // prologue: stages 0,1
    #pragma unroll
    for (int c = 0; c < NSTAGE - 1; c++) {
        load_chunk(sbase, c, c, bi, bj, tid);
        asm volatile("cp.async.commit_group;" ::: "memory");
    }

    for (int c = 0; c < NITER; c++) {
        if (c < NITER - 1)
            asm volatile("cp.async.wait_group 1;" ::: "memory");
        else
            asm volatile("cp.async.wait_group 0;" ::: "memory");
        __syncthreads();

        if (c + NSTAGE - 1 < NITER) {
            load_chunk(sbase, c + NSTAGE - 1, (c + NSTAGE - 1) % NSTAGE, bi, bj, tid);
            asm volatile("cp.async.commit_group;" ::: "memory");
        }

        const uint32_t sA = sbase + (c % NSTAGE) * STAGE_BYTES;
        const uint32_t sB = sA + A_BYTES;

        #pragma unroll
        for (int kk = 0; kk < 4; kk++) {                   // 4 x k32 (fp8)
            const int seg = (kk << 1) | lhalf;             // 16B seg 0..7
            uint32_t a[4][4], b[2][4];
            #pragma unroll
            for (int mf = 0; mf < 4; mf++) {
                int row = mw * 64 + mf * 16 + lrow;
                ldsm4(a[mf], sA + row * 128 + ((seg ^ (row & 7)) << 4));
            }
            #pragma unroll
            for (int nq = 0; nq < 2; nq++) {
                int row = nw * 32 + nq * 16 + lrow;
                ldsm4(b[nq], sB + row * 128 + ((seg ^ (row & 7)) << 4));
            }
            #pragma unroll
            for (int mf = 0; mf < 4; mf++)
                #pragma unroll
                for (int nq = 0; nq < 2; nq++) {
                    mma_fp8(acc[mf][nq * 2 + 0], a[mf], b[nq][0], b[nq][2]);
                    mma_fp8(acc[mf][nq * 2 + 1], a[mf], b[nq][1], b[nq][3]);
                }
        }
    }
    __syncthreads();   // stage smem now free for epilogue reuse

    // ---- epilogue: diag, exp, row/col partial sums ----
    float* rowp = reinterpret_cast<float*>(sm_raw);          // [4 nw][128]
    float* colp = reinterpret_cast<float*>(sm_raw) + 512;    // [2 mw][128]

    const bool hd = (bj == bi);
    const int r0 = bi * TM + mw * 64 + (lane >> 2);          // + mf*16 (+8)
    const int c0 = bj * TN + nw * 32 + 2 * (lane & 3);       // + nf*8 (+1)
    const float SC  = QSCALE * C1;       // logit->exp2 arg scale
    const float SD  = QSCALE * INV_T;    // diag scale

    float rs[4][2];
    float cs[4][2];
    #pragma unroll
    for (int mf = 0; mf < 4; mf++) { rs[mf][0] = 0.f; rs[mf][1] = 0.f; }
    #pragma unroll
    for (int nf = 0; nf < 4; nf++) { cs[nf][0] = 0.f; cs[nf][1] = 0.f; }

    #pragma unroll
    for (int mf = 0; mf < 4; mf++) {
        #pragma unroll
        for (int nf = 0; nf < 4; nf++) {
            float* v = acc[mf][nf];
            if (hd) {
                int gr0 = r0 + mf * 16, gr1 = gr0 + 8;
                int gc0 = c0 + nf * 8,  gc1 = gc0 + 1;
                if (gc0 == gr0) g_diag[gr0] = v[0] * SD;
                if (gc1 == gr0) g_diag[gr0] = v[1] * SD;
                if (gc0 == gr1) g_diag[gr1] = v[2] * SD;
                if (gc1 == gr1) g_diag[gr1] = v[3] * SD;
            }
            float e0 = exp2_fast(fmaf(v[0], SC, -C1));
            float e1 = exp2_fast(fmaf(v[1], SC, -C1));
            float e2 = exp2_fast(fmaf(v[2], SC, -C1));
            float e3 = exp2_fast(fmaf(v[3], SC, -C1));
            rs[mf][0] += e0 + e1;
            rs[mf][1] += e2 + e3;
            cs[nf][0] += e0 + e2;
            cs[nf][1] += e1 + e3;
        }
    }

    // row sums: reduce across lane&3 (cols within warp)
    #pragma unroll
    for (int mf = 0; mf < 4; mf++)
        #pragma unroll
        for (int h = 0; h < 2; h++) {
            float r = rs[mf][h];
            r += __shfl_xor_sync(0xffffffffu, r, 1);
            r += __shfl_xor_sync(0xffffffffu, r, 2);
            rs[mf][h] = r;
        }
    if ((lane & 3) == 0) {
        #pragma unroll
        for (int mf = 0; mf < 4; mf++)
            #pragma unroll
            for (int h = 0; h < 2; h++)
                rowp[nw * 128 + mw * 64 + mf * 16 + (lane >> 2) + 8 * h] = rs[mf][h];
    }

    // col sums: reduce across lane>>2 (rows within warp)
    #pragma unroll
    for (int nf = 0; nf < 4; nf++)
        #pragma unroll
        for (int e = 0; e < 2; e++) {
            float cv = cs[nf][e];
            cv += __shfl_xor_sync(0xffffffffu, cv, 4);
            cv += __shfl_xor_sync(0xffffffffu, cv, 8);
            cv += __shfl_xor_sync(0xffffffffu, cv, 16);
            cs[nf][e] = cv;
        }
    if (lane < 4) {
        #pragma unroll
        for (int nf = 0; nf < 4; nf++)
            #pragma unroll
            for (int e = 0; e < 2; e++)
                colp[mw * 128 + nw * 32 + nf * 8 + 2 * lane + e] = cs[nf][e];
    }
    __syncthreads();

    if (tid < TM) {
        g_row_part[(size_t)bj * NR + bi * TM + tid] =
            (rowp[tid] + rowp[128 + tid]) + (rowp[256 + tid] + rowp[384 + tid]);
    } else {
        int t = tid - 128;
        g_col_part[(size_t)bi * NR + bj * TN + t] = colp[t] + colp[128 + t];
    }
}

// ---------------- kernel 3: per-row lse combine + fused final (last-block ticket) ----------------
__global__ void __launch_bounds__(256) reduce_rows_kernel(float* __restrict__ out) {
    int r = blockIdx.x * 256 + threadIdx.x;
    float rs = 0.f, cs = 0.f;
    #pragma unroll 8
    for (int j = 0; j < NBJ; j++) rs += __ldcs(&g_row_part[(size_t)j * NR + r]);
    #pragma unroll 8
    for (int i = 0; i < NBI; i++) cs += __ldcs(&g_col_part[(size_t)i * NR + r]);
    float c = 0.5f * (logf(rs) + logf(cs)) + INV_T - g_diag[r];

    #pragma unroll
    for (int o = 16; o; o >>= 1) c += __shfl_xor_sync(0xffffffffu, c, o);
    __shared__ float red[8];
    __shared__ bool is_last;
    int w = threadIdx.x >> 5, l = threadIdx.x & 31;
    if (l == 0) red[w] = c;
    __syncthreads();
    if (threadIdx.x == 0) {
        float t = 0.f;
        #pragma unroll
        for (int i = 0; i < 8; i++) t += red[i];
        g_block_part[blockIdx.x] = t;
        __threadfence();
        unsigned int tk = atomicAdd(&g_ticket, 1u);
        is_last = (tk == RBLK - 1);
    }
    __syncthreads();
    if (is_last && threadIdx.x == 0) {
        __threadfence();
        volatile float* bp = g_block_part;
        float tot = 0.f;
        #pragma unroll
        for (int i = 0; i < RBLK; i++) tot += bp[i];
        out[0] = tot * (1.0f / (float)NR);
        g_ticket = 0;   // reset for next graph replay (deterministic)
    }
}

// ---------------- launch ----------------
extern "C" void kernel_launch(void* const* d_in, const int* in_sizes, int n_in,
                              void* d_out, int out_size) {
    const float* q = (const float*)d_in[0];
    const float* k = (const float*)d_in[1];
    float* out = (float*)d_out;

    cudaFuncSetAttribute(gemm_tile_kernel,
                         cudaFuncAttributeMaxDynamicSharedMemorySize, SMEM_TOTAL);

    norm_kernel<<<2 * NR / 8, 256>>>(q, k);
    gemm_tile_kernel<<<dim3(NBJ, NBI), THREADS, SMEM_TOTAL>>>();
    reduce_rows_kernel<<<RBLK, 256>>>(out);
}

// round 15
// speedup vs baseline: 1.0052x; 1.0052x over previous
#include <cuda_runtime.h>
#include <cuda_bf16.h>
#include <stdint.h>

// ---------------- constants ----------------
#define NR   8192
#define DD   1024
#define TM   128           // tile rows (Q block)
#define TN   128           // tile cols (K block)
#define NBI  (NR / TM)     // 64 row blocks
#define NBJ  (NR / TN)     // 64 col blocks
#define KB   128           // bytes per k-chunk per row = 128 fp8 = SW128 atom row
#define NITER (DD / KB)    // 8 chunks
#define NSTAGE 3
#define THREADS 256
#define A_BYTES (TM * 128)             // 16384
#define B_BYTES (TN * 128)             // 16384
#define STAGE_BYTES (A_BYTES + B_BYTES)
#define SMEM_TOTAL (NSTAGE * STAGE_BYTES)   // 98304 -> 2 CTAs/SM

#define INV_T 14.285714285714286f
#define C1    20.609929155556602f      /* (1/0.07) * log2(e) */
#define QSCALE (1.0f / 64.0f)          /* vectors scaled by 8 -> dot scaled by 64 */
#define RBLK 32                        /* reduce kernel blocks */

// ---------------- device scratch (static only) ----------------
__device__ __align__(256) char g_q8[NR * DD];
__device__ __align__(256) char g_k8[NR * DD];
__device__ float g_row_part[NBJ * NR];   // [col-block j][global row]
__device__ float g_col_part[NBI * NR];   // [row-block i][global col]
__device__ float g_diag[NR];
__device__ float g_block_part[RBLK];
__device__ unsigned int g_ticket = 0;

// ---------------- helpers ----------------
__device__ __forceinline__ uint32_t smem_u32(const void* p) {
    uint32_t a;
    asm("{ .reg .u64 t; cvta.to.shared.u64 t, %1; cvt.u32.u64 %0, t; }" : "=r"(a) : "l"(p));
    return a;
}

__device__ __forceinline__ void cp16(uint32_t dst, const void* src) {
    asm volatile("cp.async.cg.shared.global [%0], [%1], 16;" :: "r"(dst), "l"(src) : "memory");
}

__device__ __forceinline__ void ldsm4(uint32_t (&r)[4], uint32_t addr) {
    asm volatile("ldmatrix.sync.aligned.m8n8.x4.shared.b16 {%0,%1,%2,%3}, [%4];"
                 : "=r"(r[0]), "=r"(r[1]), "=r"(r[2]), "=r"(r[3]) : "r"(addr));
}

// fp8 e4m3 MMA m16n8k32, f32 accum
__device__ __forceinline__ void mma_fp8(float (&c)[4], const uint32_t (&a)[4],
                                        uint32_t b0, uint32_t b1) {
    asm volatile(
        "mma.sync.aligned.m16n8k32.row.col.f32.e4m3.e4m3.f32 "
        "{%0,%1,%2,%3}, {%4,%5,%6,%7}, {%8,%9}, {%0,%1,%2,%3};"
        : "+f"(c[0]), "+f"(c[1]), "+f"(c[2]), "+f"(c[3])
        : "r"(a[0]), "r"(a[1]), "r"(a[2]), "r"(a[3]), "r"(b0), "r"(b1));
}

// fast exp2 on the FMA pipe (no MUFU); y in [-42, ~0.5] here
__device__ __forceinline__ float exp2_fast(float y) {
    float t = y + 12582912.0f;                       // 1.5 * 2^23
    int   n = __float_as_int(t) - __float_as_int(12582912.0f);
    float f = y - (t - 12582912.0f);                 // [-0.5, 0.5]
    float p = 1.3333558146e-3f;
    p = fmaf(p, f, 9.6181291076e-3f);
    p = fmaf(p, f, 5.5504108664e-2f);
    p = fmaf(p, f, 2.4022650696e-1f);
    p = fmaf(p, f, 6.9314718056e-1f);
    p = fmaf(p, f, 1.0f);
    return __int_as_float(__float_as_int(p) + (n << 23));
}

// ---------------- kernel 1: L2-normalize rows -> e4m3 (warp per row) ----------------
__global__ void __launch_bounds__(256) norm_kernel(const float* __restrict__ q,
                                                   const float* __restrict__ k) {
    const int wid = threadIdx.x >> 5, lane = threadIdx.x & 31;
    const int gw = blockIdx.x * 8 + wid;          // 0 .. 2*NR-1
    const bool is_k = gw >= NR;
    const int row = is_k ? gw - NR : gw;
    const float4* src = reinterpret_cast<const float4*>((is_k ? k : q) + (size_t)row * DD);
    uint32_t* dst = reinterpret_cast<uint32_t*>((is_k ? g_k8 : g_q8) + (size_t)row * DD);

    float4 v[8];
    float s = 0.f;
    #pragma unroll
    for (int i = 0; i < 8; i++) {
        v[i] = src[lane + 32 * i];
        s += v[i].x * v[i].x + v[i].y * v[i].y + v[i].z * v[i].z + v[i].w * v[i].w;
    }
    #pragma unroll
    for (int o = 16; o; o >>= 1) s += __shfl_xor_sync(0xffffffffu, s, o);
    const float inv = 8.0f / fmaxf(sqrtf(s), 1e-12f);

    #pragma unroll
    for (int i = 0; i < 8; i++) {
        uint16_t lo, hi;
        asm("cvt.rn.satfinite.e4m3x2.f32 %0, %1, %2;" : "=h"(lo) : "f"(v[i].y * inv), "f"(v[i].x * inv));
        asm("cvt.rn.satfinite.e4m3x2.f32 %0, %1, %2;" : "=h"(hi) : "f"(v[i].w * inv), "f"(v[i].z * inv));
        dst[lane + 32 * i] = (uint32_t)lo | ((uint32_t)hi << 16);
    }
}

// ---------------- kernel 2: fused FP8 MMA tile (128x128, 2 CTAs/SM) ----------------
extern __shared__ char sm_raw[];

__device__ __forceinline__ void load_chunk(uint32_t sbase, int chunk, int stage,
                                           int bi, int bj, int tid) {
    uint32_t bufA = sbase + stage * STAGE_BYTES;
    uint32_t bufB = bufA + A_BYTES;
    const char* gA = g_q8 + (size_t)(bi * TM) * DD + chunk * KB;
    const char* gB = g_k8 + (size_t)(bj * TN) * DD + chunk * KB;
    #pragma unroll
    for (int u = 0; u < 4; u++) {            // A: 1024 x 16B
        int idx = tid + u * THREADS;
        int row = idx >> 3, seg = idx & 7;
        cp16(bufA + row * 128 + ((seg ^ (row & 7)) << 4),
             gA + (size_t)row * DD + seg * 16);
    }
    #pragma unroll
    for (int u = 0; u < 4; u++) {            // B: 1024 x 16B
        int idx = tid + u * THREADS;
        int row = idx >> 3, seg = idx & 7;
        cp16(bufB + row * 128 + ((seg ^ (row & 7)) << 4),
             gB + (size_t)row * DD + seg * 16);
    }
}

__global__ void __launch_bounds__(THREADS, 2) gemm_tile_kernel() {
    const int tid = threadIdx.x;
    const int bi = blockIdx.y;     // Q block: rows bi*128..+127
    const int bj = blockIdx.x;     // K block: cols bj*128..+127
    const uint32_t sbase = smem_u32(sm_raw);

    const int wid  = tid >> 5, lane = tid & 31;
    const int mw   = wid >> 2;     // 0..1 : 64-row strip
    const int nw   = wid & 3;      // 0..3 : 32-col strip
    const int lrow = lane & 15;    // row within 16-row frag
    const int lhalf = lane >> 4;   // 16B half within k32

    // hoisted ldmatrix offsets: invariant across chunks (only stage base rotates)
    uint32_t aoff[4][4], boff[4][2];
    #pragma unroll
    for (int kk = 0; kk < 4; kk++) {
        const int seg = (kk << 1) | lhalf;
        #pragma unroll
        for (int mf = 0; mf < 4; mf++) {
            int row = mw * 64 + mf * 16 + lrow;
            aoff[kk][mf] = row * 128 + ((seg ^ (row & 7)) << 4);
        }
        #pragma unroll
        for (int nq = 0; nq < 2; nq++) {
            int row = nw * 32 + nq * 16 + lrow;
            boff[kk][nq] = A_BYTES + row * 128 + ((seg ^ (row & 7)) << 4);
        }
    }

    float acc[4][4][4];
    #pragma unroll
    for (int mf = 0; mf < 4; mf++)
        #pragma unroll
        for (int nf = 0; nf < 4; nf++)
            #pragma unroll
            for (int e = 0; e < 4; e++) acc[mf][nf][e] = 0.f;

    // prologue: stages 0,1
    #pragma unroll
    for (int c = 0; c < NSTAGE - 1; c++) {
        load_chunk(sbase, c, c, bi, bj, tid);
        asm volatile("cp.async.commit_group;" ::: "memory");
    }

    for (int c = 0; c < NITER; c++) {
        if (c < NITER - 1)
            asm volatile("cp.async.wait_group 1;" ::: "memory");
        else
            asm volatile("cp.async.wait_group 0;" ::: "memory");
        __syncthreads();

        if (c + NSTAGE - 1 < NITER) {
            load_chunk(sbase, c + NSTAGE - 1, (c + NSTAGE - 1) % NSTAGE, bi, bj, tid);
            asm volatile("cp.async.commit_group;" ::: "memory");
        }

        const uint32_t sS = sbase + (c % NSTAGE) * STAGE_BYTES;

        #pragma unroll
        for (int kk = 0; kk < 4; kk++) {                   // 4 x k32 (fp8)
            uint32_t a[4][4], b[2][4];
            #pragma unroll
            for (int mf = 0; mf < 4; mf++)
                ldsm4(a[mf], sS + aoff[kk][mf]);
            #pragma unroll
            for (int nq = 0; nq < 2; nq++)
                ldsm4(b[nq], sS + boff[kk][nq]);
            #pragma unroll
            for (int mf = 0; mf < 4; mf++)
                #pragma unroll
                for (int nq = 0; nq < 2; nq++) {
                    mma_fp8(acc[mf][nq * 2 + 0], a[mf], b[nq][0], b[nq][2]);
                    mma_fp8(acc[mf][nq * 2 + 1], a[mf], b[nq][1], b[nq][3]);
                }
        }
    }
    __syncthreads();   // stage smem now free for epilogue reuse

    // ---- epilogue: diag, exp, row/col partial sums ----
    float* rowp = reinterpret_cast<float*>(sm_raw);          // [4 nw][128]
    float* colp = reinterpret_cast<float*>(sm_raw) + 512;    // [2 mw][128]

    const bool hd = (bj == bi);
    const int r0 = bi * TM + mw * 64 + (lane >> 2);          // + mf*16 (+8)
    const int c0 = bj * TN + nw * 32 + 2 * (lane & 3);       // + nf*8 (+1)
    const float SC  = QSCALE * C1;       // logit->exp2 arg scale
    const float SD  = QSCALE * INV_T;    // diag scale

    float rs[4][2];
    float cs[4][2];
    #pragma unroll
    for (int mf = 0; mf < 4; mf++) { rs[mf][0] = 0.f; rs[mf][1] = 0.f; }
    #pragma unroll
    for (int nf = 0; nf < 4; nf++) { cs[nf][0] = 0.f; cs[nf][1] = 0.f; }

    #pragma unroll
    for (int mf = 0; mf < 4; mf++) {
        #pragma unroll
        for (int nf = 0; nf < 4; nf++) {
            float* v = acc[mf][nf];
            if (hd) {
                int gr0 = r0 + mf * 16, gr1 = gr0 + 8;
                int gc0 = c0 + nf * 8,  gc1 = gc0 + 1;
                if (gc0 == gr0) g_diag[gr0] = v[0] * SD;
                if (gc1 == gr0) g_diag[gr0] = v[1] * SD;
                if (gc0 == gr1) g_diag[gr1] = v[2] * SD;
                if (gc1 == gr1) g_diag[gr1] = v[3] * SD;
            }
            float e0 = exp2_fast(fmaf(v[0], SC, -C1));
            float e1 = exp2_fast(fmaf(v[1], SC, -C1));
            float e2 = exp2_fast(fmaf(v[2], SC, -C1));
            float e3 = exp2_fast(fmaf(v[3], SC, -C1));
            rs[mf][0] += e0 + e1;
            rs[mf][1] += e2 + e3;
            cs[nf][0] += e0 + e2;
            cs[nf][1] += e1 + e3;
        }
    }

    // row sums: reduce across lane&3 (cols within warp)
    #pragma unroll
    for (int mf = 0; mf < 4; mf++)
        #pragma unroll
        for (int h = 0; h < 2; h++) {
            float r = rs[mf][h];
            r += __shfl_xor_sync(0xffffffffu, r, 1);
            r += __shfl_xor_sync(0xffffffffu, r, 2);
            rs[mf][h] = r;
        }
    if ((lane & 3) == 0) {
        #pragma unroll
        for (int mf = 0; mf < 4; mf++)
            #pragma unroll
            for (int h = 0; h < 2; h++)
                rowp[nw * 128 + mw * 64 + mf * 16 + (lane >> 2) + 8 * h] = rs[mf][h];
    }

    // col sums: reduce across lane>>2 (rows within warp)
    #pragma unroll
    for (int nf = 0; nf < 4; nf++)
        #pragma unroll
        for (int e = 0; e < 2; e++) {
            float cv = cs[nf][e];
            cv += __shfl_xor_sync(0xffffffffu, cv, 4);
            cv += __shfl_xor_sync(0xffffffffu, cv, 8);
            cv += __shfl_xor_sync(0xffffffffu, cv, 16);
            cs[nf][e] = cv;
        }
    if (lane < 4) {
        #pragma unroll
        for (int nf = 0; nf < 4; nf++)
            #pragma unroll
            for (int e = 0; e < 2; e++)
                colp[mw * 128 + nw * 32 + nf * 8 + 2 * lane + e] = cs[nf][e];
    }
    __syncthreads();

    if (tid < TM) {
        g_row_part[(size_t)bj * NR + bi * TM + tid] =
            (rowp[tid] + rowp[128 + tid]) + (rowp[256 + tid] + rowp[384 + tid]);
    } else {
        int t = tid - 128;
        g_col_part[(size_t)bi * NR + bj * TN + t] = colp[t] + colp[128 + t];
    }
}

// ---------------- kernel 3: per-row lse combine + fused final (last-block ticket) ----------------
__global__ void __launch_bounds__(256) reduce_rows_kernel(float* __restrict__ out) {
    int r = blockIdx.x * 256 + threadIdx.x;
    float rs = 0.f, cs = 0.f;
    #pragma unroll 8
    for (int j = 0; j < NBJ; j++) rs += g_row_part[(size_t)j * NR + r];
    #pragma unroll 8
    for (int i = 0; i < NBI; i++) cs += g_col_part[(size_t)i * NR + r];
    float c = 0.5f * (logf(rs) + logf(cs)) + INV_T - g_diag[r];

    #pragma unroll
    for (int o = 16; o; o >>= 1) c += __shfl_xor_sync(0xffffffffu, c, o);
    __shared__ float red[8];
    __shared__ bool is_last;
    int w = threadIdx.x >> 5, l = threadIdx.x & 31;
    if (l == 0) red[w] = c;
    __syncthreads();
    if (threadIdx.x == 0) {
        float t = 0.f;
        #pragma unroll
        for (int i = 0; i < 8; i++) t += red[i];
        g_block_part[blockIdx.x] = t;
        __threadfence();
        unsigned int tk = atomicAdd(&g_ticket, 1u);
        is_last = (tk == RBLK - 1);
    }
    __syncthreads();
    if (is_last && threadIdx.x == 0) {
        __threadfence();
        volatile float* bp = g_block_part;
        float tot = 0.f;
        #pragma unroll
        for (int i = 0; i < RBLK; i++) tot += bp[i];
        out[0] = tot * (1.0f / (float)NR);
        g_ticket = 0;   // reset for next graph replay (deterministic)
    }
}

// ---------------- launch ----------------
extern "C" void kernel_launch(void* const* d_in, const int* in_sizes, int n_in,
                              void* d_out, int out_size) {
    const float* q = (const float*)d_in[0];
    const float* k = (const float*)d_in[1];
    float* out = (float*)d_out;

    cudaFuncSetAttribute(gemm_tile_kernel,
                         cudaFuncAttributeMaxDynamicSharedMemorySize, SMEM_TOTAL);

    norm_kernel<<<2 * NR / 8, 256>>>(q, k);
    gemm_tile_kernel<<<dim3(NBJ, NBI), THREADS, SMEM_TOTAL>>>();
    reduce_rows_kernel<<<RBLK, 256>>>(out);
}

// round 16
// speedup vs baseline: 1.0094x; 1.0042x over previous
#include <cuda_runtime.h>
#include <cuda_bf16.h>
#include <stdint.h>

// ---------------- constants ----------------
#define NR   8192
#define DD   1024
#define TM   128           // tile rows (Q block)
#define TN   128           // tile cols (K block)
#define NBI  (NR / TM)     // 64 row blocks
#define NBJ  (NR / TN)     // 64 col blocks
#define KB   128           // bytes per k-chunk per row = 128 fp8 = SW128 atom row
#define NITER (DD / KB)    // 8 chunks
#define NSTAGE 3
#define THREADS 256
#define A_BYTES (TM * 128)             // 16384
#define B_BYTES (TN * 128)             // 16384
#define STAGE_BYTES (A_BYTES + B_BYTES)
#define SMEM_TOTAL (NSTAGE * STAGE_BYTES)   // 98304 -> 2 CTAs/SM

#define INV_T 14.285714285714286f
#define C1    20.609929155556602f      /* (1/0.07) * log2(e) */
#define QSCALE (1.0f / 64.0f)          /* vectors scaled by 8 -> dot scaled by 64 */
#define RBLK 32                        /* reduce kernel blocks */

// ---------------- device scratch (static only) ----------------
__device__ __align__(256) char g_q8[NR * DD];
__device__ __align__(256) char g_k8[NR * DD];
__device__ float g_row_part[NBJ * NR];   // [col-block j][global row]
__device__ float g_col_part[NBI * NR];   // [row-block i][global col]
__device__ float g_diag[NR];
__device__ float g_block_part[RBLK];
__device__ unsigned int g_ticket = 0;

// ---------------- helpers ----------------
__device__ __forceinline__ uint32_t smem_u32(const void* p) {
    uint32_t a;
    asm("{ .reg .u64 t; cvta.to.shared.u64 t, %1; cvt.u32.u64 %0, t; }" : "=r"(a) : "l"(p));
    return a;
}

__device__ __forceinline__ void cp16(uint32_t dst, const void* src) {
    asm volatile("cp.async.cg.shared.global [%0], [%1], 16;" :: "r"(dst), "l"(src) : "memory");
}

__device__ __forceinline__ void ldsm4(uint32_t (&r)[4], uint32_t addr) {
    asm volatile("ldmatrix.sync.aligned.m8n8.x4.shared.b16 {%0,%1,%2,%3}, [%4];"
                 : "=r"(r[0]), "=r"(r[1]), "=r"(r[2]), "=r"(r[3]) : "r"(addr));
}

// fp8 e4m3 MMA m16n8k32, f32 accum
__device__ __forceinline__ void mma_fp8(float (&c)[4], const uint32_t (&a)[4],
                                        uint32_t b0, uint32_t b1) {
    asm volatile(
        "mma.sync.aligned.m16n8k32.row.col.f32.e4m3.e4m3.f32 "
        "{%0,%1,%2,%3}, {%4,%5,%6,%7}, {%8,%9}, {%0,%1,%2,%3};"
        : "+f"(c[0]), "+f"(c[1]), "+f"(c[2]), "+f"(c[3])
        : "r"(a[0]), "r"(a[1]), "r"(a[2]), "r"(a[3]), "r"(b0), "r"(b1));
}

// fast exp2 on the FMA pipe (no MUFU); y in [-42, ~0.5] here
__device__ __forceinline__ float exp2_fast(float y) {
    float t = y + 12582912.0f;                       // 1.5 * 2^23
    int   n = __float_as_int(t) - __float_as_int(12582912.0f);
    float f = y - (t - 12582912.0f);                 // [-0.5, 0.5]
    float p = 1.3333558146e-3f;
    p = fmaf(p, f, 9.6181291076e-3f);
    p = fmaf(p, f, 5.5504108664e-2f);
    p = fmaf(p, f, 2.4022650696e-1f);
    p = fmaf(p, f, 6.9314718056e-1f);
    p = fmaf(p, f, 1.0f);
    return __int_as_float(__float_as_int(p) + (n << 23));
}

// ---------------- kernel 1: L2-normalize rows -> e4m3 (warp per row) ----------------
__global__ void __launch_bounds__(256) norm_kernel(const float* __restrict__ q,
                                                   const float* __restrict__ k) {
    const int wid = threadIdx.x >> 5, lane = threadIdx.x & 31;
    const int gw = blockIdx.x * 8 + wid;          // 0 .. 2*NR-1
    const bool is_k = gw >= NR;
    const int row = is_k ? gw - NR : gw;
    const float4* src = reinterpret_cast<const float4*>((is_k ? k : q) + (size_t)row * DD);
    uint32_t* dst = reinterpret_cast<uint32_t*>((is_k ? g_k8 : g_q8) + (size_t)row * DD);

    float4 v[8];
    float s = 0.f;
    #pragma unroll
    for (int i = 0; i < 8; i++) {
        v[i] = src[lane + 32 * i];
        s += v[i].x * v[i].x + v[i].y * v[i].y + v[i].z * v[i].z + v[i].w * v[i].w;
    }
    #pragma unroll
    for (int o = 16; o; o >>= 1) s += __shfl_xor_sync(0xffffffffu, s, o);
    const float inv = 8.0f / fmaxf(sqrtf(s), 1e-12f);

    #pragma unroll
    for (int i = 0; i < 8; i++) {
        uint16_t lo, hi;
        asm("cvt.rn.satfinite.e4m3x2.f32 %0, %1, %2;" : "=h"(lo) : "f"(v[i].y * inv), "f"(v[i].x * inv));
        asm("cvt.rn.satfinite.e4m3x2.f32 %0, %1, %2;" : "=h"(hi) : "f"(v[i].w * inv), "f"(v[i].z * inv));
        dst[lane + 32 * i] = (uint32_t)lo | ((uint32_t)hi << 16);
    }
}

// ---------------- kernel 2: fused FP8 MMA tile (128x128, 2 CTAs/SM) ----------------
extern __shared__ char sm_raw[];

__device__ __forceinline__ void load_chunk(uint32_t sbase, int chunk, int stage,
                                           int bi, int bj, int tid) {
    uint32_t bufA = sbase + stage * STAGE_BYTES;
    uint32_t bufB = bufA + A_BYTES;
    const char* gA = g_q8 + (size_t)(bi * TM) * DD + chunk * KB;
    const char* gB = g_k8 + (size_t)(bj * TN) * DD + chunk * KB;
    #pragma unroll
    for (int u = 0; u < 4; u++) {            // A: 1024 x 16B
        int idx = tid + u * THREADS;
        int row = idx >> 3, seg = idx & 7;
        cp16(bufA + row * 128 + ((seg ^ (row & 7)) << 4),
             gA + (size_t)row * DD + seg * 16);
    }
    #pragma unroll
    for (int u = 0; u < 4; u++) {            // B: 1024 x 16B
        int idx = tid + u * THREADS;
        int row = idx >> 3, seg = idx & 7;
        cp16(bufB + row * 128 + ((seg ^ (row & 7)) << 4),
             gB + (size_t)row * DD + seg * 16);
    }
}

__global__ void __launch_bounds__(THREADS, 2) gemm_tile_kernel() {
    const int tid = threadIdx.x;
    const int bi = blockIdx.y;     // Q block: rows bi*128..+127
    const int bj = blockIdx.x;     // K block: cols bj*128..+127
    const uint32_t sbase = smem_u32(sm_raw);

    const int wid  = tid >> 5, lane = tid & 31;
    const int mw   = wid >> 2;     // 0..1 : 64-row strip
    const int nw   = wid & 3;      // 0..3 : 32-col strip
    const int lrow = lane & 15;    // row within 16-row frag
    const int lhalf = lane >> 4;   // 16B half within k32

    // hoisted ldmatrix offsets: invariant across chunks (only stage base rotates)
    uint32_t aoff[4][4], boff[4][2];
    #pragma unroll
    for (int kk = 0; kk < 4; kk++) {
        const int seg = (kk << 1) | lhalf;
        #pragma unroll
        for (int mf = 0; mf < 4; mf++) {
            int row = mw * 64 + mf * 16 + lrow;
            aoff[kk][mf] = row * 128 + ((seg ^ (row & 7)) << 4);
        }
        #pragma unroll
        for (int nq = 0; nq < 2; nq++) {
            int row = nw * 32 + nq * 16 + lrow;
            boff[kk][nq] = A_BYTES + row * 128 + ((seg ^ (row & 7)) << 4);
        }
    }

    float acc[4][4][4];
    #pragma unroll
    for (int mf = 0; mf < 4; mf++)
        #pragma unroll
        for (int nf = 0; nf < 4; nf++)
            #pragma unroll
            for (int e = 0; e < 4; e++) acc[mf][nf][e] = 0.f;

    // prologue: stages 0,1
    #pragma unroll
    for (int c = 0; c < NSTAGE - 1; c++) {
        load_chunk(sbase, c, c, bi, bj, tid);
        asm volatile("cp.async.commit_group;" ::: "memory");
    }

    for (int c = 0; c < NITER; c++) {
        if (c < NITER - 1)
            asm volatile("cp.async.wait_group 1;" ::: "memory");
        else
            asm volatile("cp.async.wait_group 0;" ::: "memory");
        __syncthreads();

        if (c + NSTAGE - 1 < NITER) {
            load_chunk(sbase, c + NSTAGE - 1, (c + NSTAGE - 1) % NSTAGE, bi, bj, tid);
            asm volatile("cp.async.commit_group;" ::: "memory");
        }

        const uint32_t sS = sbase + (c % NSTAGE) * STAGE_BYTES;

        #pragma unroll
        for (int kk = 0; kk < 4; kk++) {                   // 4 x k32 (fp8)
            uint32_t a[4][4], b[2][4];
            #pragma unroll
            for (int mf = 0; mf < 4; mf++)
                ldsm4(a[mf], sS + aoff[kk][mf]);
            #pragma unroll
            for (int nq = 0; nq < 2; nq++)
                ldsm4(b[nq], sS + boff[kk][nq]);
            #pragma unroll
            for (int mf = 0; mf < 4; mf++)
                #pragma unroll
                for (int nq = 0; nq < 2; nq++) {
                    mma_fp8(acc[mf][nq * 2 + 0], a[mf], b[nq][0], b[nq][2]);
                    mma_fp8(acc[mf][nq * 2 + 1], a[mf], b[nq][1], b[nq][3]);
                }
        }
    }
    __syncthreads();   // stage smem now free for epilogue reuse

    // ---- epilogue: diag, exp, row/col partial sums ----
    float* rowp = reinterpret_cast<float*>(sm_raw);          // [4 nw][128]
    float* colp = reinterpret_cast<float*>(sm_raw) + 512;    // [2 mw][128]

    const bool hd = (bj == bi);
    const int r0 = bi * TM + mw * 64 + (lane >> 2);          // + mf*16 (+8)
    const int c0 = bj * TN + nw * 32 + 2 * (lane & 3);       // + nf*8 (+1)
    const float SC  = QSCALE * C1;       // logit->exp2 arg scale
    const float SD  = QSCALE * INV_T;    // diag scale

    float rs[4][2];
    float cs[4][2];
    #pragma unroll
    for (int mf = 0; mf < 4; mf++) { rs[mf][0] = 0.f; rs[mf][1] = 0.f; }
    #pragma unroll
    for (int nf = 0; nf < 4; nf++) { cs[nf][0] = 0.f; cs[nf][1] = 0.f; }

    #pragma unroll
    for (int mf = 0; mf < 4; mf++) {
        #pragma unroll
        for (int nf = 0; nf < 4; nf++) {
            float* v = acc[mf][nf];
            if (hd) {
                int gr0 = r0 + mf * 16, gr1 = gr0 + 8;
                int gc0 = c0 + nf * 8,  gc1 = gc0 + 1;
                if (gc0 == gr0) g_diag[gr0] = v[0] * SD;
                if (gc1 == gr0) g_diag[gr0] = v[1] * SD;
                if (gc0 == gr1) g_diag[gr1] = v[2] * SD;
                if (gc1 == gr1) g_diag[gr1] = v[3] * SD;
            }
            float e0 = exp2_fast(fmaf(v[0], SC, -C1));
            float e1 = exp2_fast(fmaf(v[1], SC, -C1));
            float e2 = exp2_fast(fmaf(v[2], SC, -C1));
            float e3 = exp2_fast(fmaf(v[3], SC, -C1));
            rs[mf][0] += e0 + e1;
            rs[mf][1] += e2 + e3;
            cs[nf][0] += e0 + e2;
            cs[nf][1] += e1 + e3;
        }
    }

    // row sums: reduce across lane&3 (cols within warp)
    #pragma unroll
    for (int mf = 0; mf < 4; mf++)
        #pragma unroll
        for (int h = 0; h < 2; h++) {
            float r = rs[mf][h];
            r += __shfl_xor_sync(0xffffffffu, r, 1);
            r += __shfl_xor_sync(0xffffffffu, r, 2);
            rs[mf][h] = r;
        }
    if ((lane & 3) == 0) {
        #pragma unroll
        for (int mf = 0; mf < 4; mf++)
            #pragma unroll
            for (int h = 0; h < 2; h++)
                rowp[nw * 128 + mw * 64 + mf * 16 + (lane >> 2) + 8 * h] = rs[mf][h];
    }

    // col sums: reduce across lane>>2 (rows within warp)
    #pragma unroll
    for (int nf = 0; nf < 4; nf++)
        #pragma unroll
        for (int e = 0; e < 2; e++) {
            float cv = cs[nf][e];
            cv += __shfl_xor_sync(0xffffffffu, cv, 4);
            cv += __shfl_xor_sync(0xffffffffu, cv, 8);
            cv += __shfl_xor_sync(0xffffffffu, cv, 16);
            cs[nf][e] = cv;
        }
    if (lane < 4) {
        #pragma unroll
        for (int nf = 0; nf < 4; nf++)
            #pragma unroll
            for (int e = 0; e < 2; e++)
                colp[mw * 128 + nw * 32 + nf * 8 + 2 * lane + e] = cs[nf][e];
    }
    __syncthreads();

    if (tid < TM) {
        g_row_part[(size_t)bj * NR + bi * TM + tid] =
            (rowp[tid] + rowp[128 + tid]) + (rowp[256 + tid] + rowp[384 + tid]);
    } else {
        int t = tid - 128;
        g_col_part[(size_t)bi * NR + bj * TN + t] = colp[t] + colp[128 + t];
    }
}

// ---------------- kernel 3: per-row lse combine + fused final (last-block ticket) ----------------
__global__ void __launch_bounds__(256) reduce_rows_kernel(float* __restrict__ out) {
    int r = blockIdx.x * 256 + threadIdx.x;
    float rs = 0.f, cs = 0.f;
    #pragma unroll 8
    for (int j = 0; j < NBJ; j++) rs += g_row_part[(size_t)j * NR + r];
    #pragma unroll 8
    for (int i = 0; i < NBI; i++) cs += g_col_part[(size_t)i * NR + r];
    float c = 0.5f * (logf(rs) + logf(cs)) + INV_T - g_diag[r];

    #pragma unroll
    for (int o = 16; o; o >>= 1) c += __shfl_xor_sync(0xffffffffu, c, o);
    __shared__ float red[8];
    __shared__ bool is_last;
    int w = threadIdx.x >> 5, l = threadIdx.x & 31;
    if (l == 0) red[w] = c;
    __syncthreads();
    if (threadIdx.x == 0) {
        float t = 0.f;
        #pragma unroll
        for (int i = 0; i < 8; i++) t += red[i];
        g_block_part[blockIdx.x] = t;
        __threadfence();
        unsigned int tk = atomicAdd(&g_ticket, 1u);
        is_last = (tk == RBLK - 1);
    }
    __syncthreads();
    if (is_last && threadIdx.x == 0) {
        __threadfence();
        volatile float* bp = g_block_part;
        float tot = 0.f;
        #pragma unroll
        for (int i = 0; i < RBLK; i++) tot += bp[i];
        out[0] = tot * (1.0f / (float)NR);
        g_ticket = 0;   // reset for next graph replay (deterministic)
    }
}

// ---------------- launch ----------------
extern "C" void kernel_launch(void* const* d_in, const int* in_sizes, int n_in,
                              void* d_out, int out_size) {
    const float* q = (const float*)d_in[0];
    const float* k = (const float*)d_in[1];
    float* out = (float*)d_out;

    cudaFuncSetAttribute(gemm_tile_kernel,
                         cudaFuncAttributeMaxDynamicSharedMemorySize, SMEM_TOTAL);

    norm_kernel<<<2 * NR / 8, 256>>>(q, k);
    gemm_tile_kernel<<<dim3(NBJ, NBI), THREADS, SMEM_TOTAL>>>();
    reduce_rows_kernel<<<RBLK, 256>>>(out);
}